// round 4
// baseline (speedup 1.0000x reference)
#include <cuda_runtime.h>
#include <math.h>

#define NB   2048
#define NDIM 128
#define MLZ  10
#define KAPPA 0.276f
#define TRI  8256      // 128*129/2
#define LPAD 8448      // packed tri, rows padded to multiple of 4 floats

// dynamic smem: Lp[8448] | vcur[128] | vprev[128] | yv[128] | tv[128] | U1s[128] | tslab[512]
#define SMEM_FLOATS (LPAD + 5 * NDIM + 512)
#define SMEM_BYTES  (SMEM_FLOATS * 4)

__device__ float    g_scr[2 * NB];   // [0..NB) max^2, [NB..2NB) min^2
__device__ unsigned g_ctr = 0;

__device__ __forceinline__ float blockReduceSum256(float v, float* red, int tid) {
    #pragma unroll
    for (int o = 16; o > 0; o >>= 1)
        v += __shfl_xor_sync(0xffffffffu, v, o);
    __syncthreads();                       // protect red[] from previous use
    if ((tid & 31) == 0) red[tid >> 5] = v;
    __syncthreads();
    return ((red[0] + red[1]) + (red[2] + red[3]))
         + ((red[4] + red[5]) + (red[6] + red[7]));
}

__device__ __forceinline__ int sturm_count(const float* a, const float* b2, float x) {
    float q = a[0] - x;
    int c = (q < 0.0f);
    #pragma unroll
    for (int i = 1; i < MLZ; i++) {
        float d = q;
        if (fabsf(d) < 1e-25f) d = (d < 0.0f) ? -1e-25f : 1e-25f;
        q = (a[i] - x) - b2[i - 1] / d;
        c += (q < 0.0f);
    }
    return c;
}

__global__ __launch_bounds__(256)
void spectrum_kernel(const float* __restrict__ net_out,
                     const float* __restrict__ U1,
                     const float* __restrict__ vin,
                     float* __restrict__ out) {
    extern __shared__ float sm[];
    float* Lp    = sm;                 // row i (g=i>>2, rm=i&3) at float4 idx (g+1)*(2g+rm)
    float* vcur  = sm + LPAD;
    float* vprev = vcur + NDIM;
    float* yv    = vprev + NDIM;
    float* tv    = yv + NDIM;
    float* U1s   = tv + NDIM;
    float* tslab = U1s + NDIM;         // 4 x 128

    __shared__ float red[8];
    __shared__ float alph[MLZ], bet[MLZ], sc[4];
    __shared__ int   amLast;

    const int tid  = threadIdx.x;
    const int b    = blockIdx.x;
    const int w    = tid >> 5;
    const int lane = tid & 31;

    // ---- zero Lp (padding must be 0) ----
    {
        float4 z = make_float4(0.f, 0.f, 0.f, 0.f);
        float4* L4 = (float4*)Lp;
        #pragma unroll 2
        for (int i = tid; i < LPAD / 4; i += 256) L4[i] = z;
    }
    if (tid < NDIM) U1s[tid] = U1[(size_t)b * NDIM + tid];
    float v0 = (tid < NDIM) ? vin[(size_t)b * NDIM + tid] : 0.0f;
    __syncthreads();

    // ---- build padded packed Lp from gmem packed tri (coalesced float4 reads) ----
    {
        const float4* src4 = (const float4*)(net_out + (size_t)b * TRI);
        for (int idx = tid; idx < TRI / 4; idx += 256) {
            float4 v4 = src4[idx];
            int k = idx << 2;
            int i = (int)((__fsqrt_rn(8.0f * (float)k + 1.0f) - 1.0f) * 0.5f);
            while ((i + 1) * (i + 2) / 2 <= k) ++i;
            while (i * (i + 1) / 2 > k) --i;
            int j = k - i * (i + 1) / 2;
            float vals[4] = {v4.x, v4.y, v4.z, v4.w};
            #pragma unroll
            for (int m = 0; m < 4; m++) {
                int gi = i >> 2, ri = i & 3;
                Lp[4 * (gi + 1) * (2 * gi + ri) + j] = vals[m];
                if (++j > i) { ++i; j = 0; }
            }
        }
    }

    // vn = v / ||v||  (reduce barriers also publish Lp/U1s)
    float nrm = sqrtf(blockReduceSum256(v0 * v0, red, tid));
    if (tid < NDIM) { vcur[tid] = v0 / nrm; vprev[tid] = 0.0f; }

    // ---- dd_opt stencil constants (element = tid for tid<128) ----
    const int te  = tid & 127;
    const int ii = te >> 4, jj = (te >> 1) & 7, cc = te & 1;
    const int xip = (((ii + 1) & 7) << 4) | (jj << 1) | cc;
    const int xim = (((ii - 1) & 7) << 4) | (jj << 1) | cc;
    const int xjp = (ii << 4) | (((jj + 1) & 7) << 1) | cc;
    const int xjm = (ii << 4) | (((jj - 1) & 7) << 1) | cc;
    __syncthreads();   // U1s + vcur visible
    const float c_u0  = U1s[((ii << 3) + jj) << 1];
    const float c_u1  = U1s[(((ii << 3) + jj) << 1) + 1];
    const float c_u0m = U1s[((((ii - 1) & 7) << 3) + jj) << 1];
    const float c_u1m = U1s[(((ii << 3) + ((jj - 1) & 7)) << 1) + 1];

    // column matvec constants: warp w handles rows i = w + 8r
    const int w4 = w >> 2;            // contributes to g exactly (no carry: w<8)
    const int wrm = w & 3;            // i & 3 for all this warp's rows
    // row matvec constants: thread pair per row
    const int ih = tid >> 1, hh = tid & 1;
    const int gg = ih >> 2;
    const int rb4 = (gg + 1) * (2 * gg + (ih & 3));
    const float4* Lr4 = (const float4*)Lp;
    const float4* tv4 = (const float4*)tv;

    float beta = 0.0f;

    for (int step = 0; step < MLZ; step++) {
        // ---- y = D x (hop stencil), element = tid < 128 ----
        if (tid < NDIM) {
            float xc  = vcur[tid];
            float hop = c_u0  * vcur[xip] + c_u1  * vcur[xjp]
                      + c_u0m * vcur[xim] + c_u1m * vcur[xjm];
            yv[tid] = xc - KAPPA * hop;
        }
        __syncthreads();

        // ---- t = L^T y : warp-per-row register accumulation ----
        {
            float4 a0 = make_float4(0.f, 0.f, 0.f, 0.f);
            float4 a1 = make_float4(0.f, 0.f, 0.f, 0.f);
            #pragma unroll
            for (int r = 0; r < 16; r++) {
                const int i  = w + (r << 3);
                const int g  = (r << 1) + w4;
                const int fb = (((g + 1) * ((g << 1) + wrm)) << 2) + (lane << 2);
                float yi = yv[i];                       // uniform broadcast
                if (lane <= g) {
                    float4 l4 = *(const float4*)(Lp + fb);
                    if (r & 1) {
                        a1.x += l4.x * yi; a1.y += l4.y * yi;
                        a1.z += l4.z * yi; a1.w += l4.w * yi;
                    } else {
                        a0.x += l4.x * yi; a0.y += l4.y * yi;
                        a0.z += l4.z * yi; a0.w += l4.w * yi;
                    }
                }
            }
            a0.x += a1.x; a0.y += a1.y; a0.z += a1.z; a0.w += a1.w;

            // combine 8 warps -> 4 slabs -> tv
            if (w < 4) *(float4*)(tslab + (w << 7) + (lane << 2)) = a0;
            __syncthreads();
            if (w >= 4) {
                float4* p = (float4*)(tslab + ((w - 4) << 7) + (lane << 2));
                float4 o = *p;
                o.x += a0.x; o.y += a0.y; o.z += a0.z; o.w += a0.w;
                *p = o;
            }
            __syncthreads();
            if (tid < NDIM)
                tv[tid] = (tslab[tid] + tslab[128 + tid])
                        + (tslab[256 + tid] + tslab[384 + tid]);
            __syncthreads();
        }

        // ---- w = L t : thread-pair per row, float4, h-split ----
        {
            float ax = 0.f, ay = 0.f, az = 0.f, aw = 0.f;
            #pragma unroll 4
            for (int q = hh; q <= gg; q += 2) {
                float4 l  = Lr4[rb4 + q];
                float4 t4 = tv4[q];
                ax += l.x * t4.x; ay += l.y * t4.y;
                az += l.z * t4.z; aw += l.w * t4.w;
            }
            float wacc = (ax + ay) + (az + aw);
            wacc += __shfl_xor_sync(0xffffffffu, wacc, 1);
            if (hh == 0) yv[ih] = wacc;        // yv reuse: w vector (yv dead after col phase)
        }
        __syncthreads();

        // ---- Lanczos recurrence (element = tid < 128) ----
        float wv = (tid < NDIM) ? yv[tid] : 0.0f;
        float vc = (tid < NDIM) ? vcur[tid] : 0.0f;
        float vp = (tid < NDIM) ? vprev[tid] : 0.0f;
        float al = blockReduceSum256(wv * vc, red, tid);
        float wn = wv - al * vc - beta * vp;
        float bn = sqrtf(blockReduceSum256((tid < NDIM) ? wn * wn : 0.0f, red, tid));
        if (tid == 0) { alph[step] = al; bet[step] = bn; }
        if (tid < NDIM) {
            vprev[tid] = vc;
            vcur[tid]  = wn / (bn + 1e-30f);
        }
        beta = bn;
        __syncthreads();
    }

    // ---- 4 needed eigenvalues via Sturm bisection ----
    if (tid < 4) {
        float a[MLZ], b2[MLZ - 1];
        #pragma unroll
        for (int i = 0; i < MLZ; i++) a[i] = alph[i];
        #pragma unroll
        for (int i = 0; i < MLZ - 1; i++) { float bb = bet[i]; b2[i] = bb * bb; }

        float lo = 3.0e38f, hi = -3.0e38f;
        #pragma unroll
        for (int i = 0; i < MLZ; i++) {
            float rad = 0.0f;
            if (i > 0)       rad += fabsf(bet[i - 1]);
            if (i < MLZ - 1) rad += fabsf(bet[i]);
            lo = fminf(lo, a[i] - rad);
            hi = fmaxf(hi, a[i] + rad);
        }

        int nneg = sturm_count(a, b2, 0.0f);
        int k;
        if      (tid == 0) k = 0;
        else if (tid == 1) k = MLZ - 1;
        else if (tid == 2) { k = nneg - 1; if (k < 0) k = 0; if (k > MLZ - 1) k = MLZ - 1; }
        else               { k = nneg;     if (k > MLZ - 1) k = MLZ - 1; }

        float l = lo, h = hi;
        #pragma unroll 1
        for (int it = 0; it < 44; it++) {
            float mid = 0.5f * (l + h);
            if (sturm_count(a, b2, mid) > k) h = mid; else l = mid;
        }
        sc[tid] = fabsf(0.5f * (l + h));
    }
    __syncthreads();
    if (tid == 0) {
        float mx = fmaxf(sc[0], sc[1]);
        float mn = fminf(sc[2], sc[3]);
        g_scr[b]      = mx * mx;
        g_scr[NB + b] = mn * mn;
        __threadfence();
        unsigned t = atomicAdd(&g_ctr, 1u);
        amLast = (t == NB - 1);
    }
    __syncthreads();

    // ---- last CTA reduces all batches (fixed order => deterministic) ----
    if (amLast) {
        __threadfence();
        const volatile float* scr = g_scr;
        float s1 = 0.0f, s2 = 0.0f;
        for (int i = tid; i < NB; i += 256) { s1 += scr[i]; s2 += scr[NB + i]; }
        float S1 = blockReduceSum256(s1, red, tid);
        __syncthreads();
        float S2 = blockReduceSum256(s2, red, tid);
        if (tid == 0) {
            out[0] = (S1 - S2) * (1.0f / (float)NB);
            g_ctr = 0;   // reset for next graph replay
        }
    }
}

extern "C" void kernel_launch(void* const* d_in, const int* in_sizes, int n_in,
                              void* d_out, int out_size) {
    const float* net_out = (const float*)d_in[0];
    const float* U1      = (const float*)d_in[1];
    const float* v       = (const float*)d_in[2];
    (void)in_sizes; (void)n_in; (void)out_size;

    static int attr_set = 0;
    if (!attr_set) {
        cudaFuncSetAttribute(spectrum_kernel,
                             cudaFuncAttributeMaxDynamicSharedMemorySize, SMEM_BYTES);
        attr_set = 1;
    }
    spectrum_kernel<<<NB, 256, SMEM_BYTES>>>(net_out, U1, v, (float*)d_out);
}